// round 10
// baseline (speedup 1.0000x reference)
#include <cuda_runtime.h>
#include <cuda_fp16.h>
#include <cuda_fp8.h>
#include <math.h>

// Problem shape (fixed by the dataset)
#define Bc 8
#define Dc 128
#define Nc 4096           // 64*64
#define TEMP_INV 10.0f    // 1 / 0.1
#define TN 32             // n-tile width in normalize

// Scratch (allocation-free rule: __device__ globals).
// Normalized features stored fp8 e4m3, permuted-d packing (word L of vector v
// holds d = L, L+32, L+64, L+96). Same permutation on both dot operands ->
// dot unchanged.
__device__ unsigned g_fp8[Bc * Nc * 32];           // 4.2 MB
__device__ uint2 g_pairoff[262144];                // per-item (vec_i, vec_j) uint4-offsets
__device__ float g_partial[16384];                 // per-block partial loss sums
__device__ int g_count = 0;                        // last-block counter (self-resetting)

// ---------------------------------------------------------------------------
// Kernel 1: L2-normalize + transpose (B,D,N)->(B,N,D) fp8, PLUS index
// precompute tail (256 pair-items per block -> offsets for the gather).
// ---------------------------------------------------------------------------
__global__ void __launch_bounds__(256, 8) normalize_kernel(
        const float* __restrict__ in,
        const int* __restrict__ pb, const int* __restrict__ pi,
        const int* __restrict__ pj, const int* __restrict__ nb,
        const int* __restrict__ ni, const int* __restrict__ nj, int P) {
    __shared__ float tile[Dc][33];
    __shared__ float psum[32][33];

    const int b      = blockIdx.y;
    const int n_base = blockIdx.x * TN;
    const int t      = threadIdx.x;
    const int r      = t >> 3;
    const int q      = t & 7;

    const float4* src = (const float4*)(in + (size_t)b * Dc * Nc + n_base);

    float4 v[4];
    #pragma unroll
    for (int k = 0; k < 4; k++)
        v[k] = src[(size_t)(r + 32 * k) * (Nc / 4) + q];

    // Index precompute tail (independent of the tile; issued early, overlaps)
    {
        const int blk = blockIdx.y * gridDim.x + blockIdx.x;   // 0..1023
        const int item = blk * 256 + t;                        // 0..262143
        if (item < 2 * P) {
            const bool neg = (item >= P);
            const int p  = neg ? item - P : item;
            const int bb = neg ? nb[p] : pb[p];
            const int ii = neg ? ni[p] : pi[p];
            const int jj = neg ? nj[p] : pj[p];
            g_pairoff[item] = make_uint2((unsigned)((bb * Nc + ii) * 8),
                                         (unsigned)((bb * Nc + jj) * 8));
        }
    }

    // Register partial sums of squares for the 4 owned columns
    float s0 = 0.f, s1 = 0.f, s2 = 0.f, s3 = 0.f;
    #pragma unroll
    for (int k = 0; k < 4; k++) {
        s0 += v[k].x * v[k].x;
        s1 += v[k].y * v[k].y;
        s2 += v[k].z * v[k].z;
        s3 += v[k].w * v[k].w;
    }
    psum[r][4 * q + 0] = s0;
    psum[r][4 * q + 1] = s1;
    psum[r][4 * q + 2] = s2;
    psum[r][4 * q + 3] = s3;

    #pragma unroll
    for (int k = 0; k < 4; k++) {
        tile[r + 32 * k][4 * q + 0] = v[k].x;
        tile[r + 32 * k][4 * q + 1] = v[k].y;
        tile[r + 32 * k][4 * q + 2] = v[k].z;
        tile[r + 32 * k][4 * q + 3] = v[k].w;
    }
    __syncthreads();

    // Write phase: warp w writes vectors n0 = w + 8i. All 4 butterfly
    // reductions interleaved -> one overlapped SHFL chain instead of 4 serial.
    const int wid = t >> 5, lane = t & 31;
    float sv[4];
    #pragma unroll
    for (int i = 0; i < 4; i++)
        sv[i] = psum[lane][wid + 8 * i];
    #pragma unroll
    for (int off = 16; off; off >>= 1) {
        #pragma unroll
        for (int i = 0; i < 4; i++)
            sv[i] += __shfl_xor_sync(0xffffffffu, sv[i], off);
    }

    #pragma unroll
    for (int i = 0; i < 4; i++) {
        const int n0 = wid + 8 * i;
        const float inv = 1.0f / fmaxf(sqrtf(sv[i]), 1e-12f);  // F.normalize eps

        // lane owns d = lane + 32k (conflict-free: bank = lane + n0)
        float d0 = tile[lane][n0]      * inv;
        float d1 = tile[lane + 32][n0] * inv;
        float d2 = tile[lane + 64][n0] * inv;
        float d3 = tile[lane + 96][n0] * inv;

        __nv_fp8x2_storage_t lo =
            __nv_cvt_float2_to_fp8x2(make_float2(d0, d1), __NV_SATFINITE, __NV_E4M3);
        __nv_fp8x2_storage_t hi =
            __nv_cvt_float2_to_fp8x2(make_float2(d2, d3), __NV_SATFINITE, __NV_E4M3);
        unsigned w32 = (unsigned)lo | ((unsigned)hi << 16);

        g_fp8[((size_t)(b * Nc + n_base + n0)) * 32 + lane] = w32;
    }
}

// ---------------------------------------------------------------------------
// Kernel 2: octet-per-dot fp8 gather + fused deterministic finalize.
// Per thread: 1 broadcast LDG.64 (precomputed offsets) + 2 LDG.128 +
// cvt/hfma2 + 3 shfls. Last-arriving block reduces g_partial in fixed order.
// ---------------------------------------------------------------------------
__global__ void gather_kernel(int P, float* __restrict__ out) {
    const int t    = threadIdx.x;
    const int ol   = t & 7;                      // lane within octet
    const int item = blockIdx.x * 64 + (t >> 3); // global octet = item index

    float val = 0.f;
    if (item < 2 * P) {
        const uint2 off = g_pairoff[item];       // broadcast within octet

        const uint4* g4 = (const uint4*)g_fp8;
        uint4 a = g4[off.x + ol];
        uint4 c = g4[off.y + ol];

        __half2 acc = __float2half2_rn(0.f);
        const unsigned* pa = &a.x;
        const unsigned* pc = &c.x;
        #pragma unroll
        for (int m = 0; m < 4; m++) {
            __half2 alo = __half2(__nv_cvt_fp8x2_to_halfraw2(
                (__nv_fp8x2_storage_t)(pa[m] & 0xffffu), __NV_E4M3));
            __half2 clo = __half2(__nv_cvt_fp8x2_to_halfraw2(
                (__nv_fp8x2_storage_t)(pc[m] & 0xffffu), __NV_E4M3));
            acc = __hfma2(alo, clo, acc);
            __half2 ahi = __half2(__nv_cvt_fp8x2_to_halfraw2(
                (__nv_fp8x2_storage_t)(pa[m] >> 16), __NV_E4M3));
            __half2 chi = __half2(__nv_cvt_fp8x2_to_halfraw2(
                (__nv_fp8x2_storage_t)(pc[m] >> 16), __NV_E4M3));
            acc = __hfma2(ahi, chi, acc);
        }
        float2 f = __half22float2(acc);
        float dot = f.x + f.y;

        dot += __shfl_xor_sync(0xffffffffu, dot, 1);
        dot += __shfl_xor_sync(0xffffffffu, dot, 2);
        dot += __shfl_xor_sync(0xffffffffu, dot, 4);

        if (ol == 0) {
            float s = dot * TEMP_INV;
            float x = (item >= P) ? s : -s;      // softplus(x) = -log_sigmoid(-x)
            val = fmaxf(x, 0.f) + log1pf(expf(-fabsf(x)));
        }
    }

    // Block reduction: 64 octet-leader values -> fixed-order tree
    __shared__ float sred[64];
    if (ol == 0) sred[t >> 3] = val;
    __syncthreads();
    if (t < 32) {
        float s = sred[t] + sred[t + 32];
        #pragma unroll
        for (int o = 16; o; o >>= 1)
            s += __shfl_xor_sync(0xffffffffu, s, o);
        if (t == 0) g_partial[blockIdx.x] = s;
    }

    // Fused finalize: last-arriving block does a fixed-order reduce of all
    // partials (deterministic bits; the atomic only orders the int counter).
    __shared__ int is_last;
    __threadfence();
    __syncthreads();
    if (t == 0)
        is_last = (atomicAdd(&g_count, 1) == (int)gridDim.x - 1) ? 1 : 0;
    __syncthreads();
    if (is_last) {
        const int nblocks = (int)gridDim.x;
        __shared__ float fred[512];
        float s = 0.f;
        for (int k = t; k < nblocks; k += 512) s += g_partial[k];
        fred[t] = s;
        __syncthreads();
        #pragma unroll
        for (int stride = 256; stride; stride >>= 1) {
            if (t < stride) fred[t] += fred[t + stride];
            __syncthreads();
        }
        if (t == 0) {
            out[0] = fred[0] / (float)P;
            g_count = 0;                     // reset for next graph replay
        }
    }
}

extern "C" void kernel_launch(void* const* d_in, const int* in_sizes, int n_in,
                              void* d_out, int out_size) {
    const float* feats = (const float*)d_in[0];
    const int*   pb    = (const int*)d_in[1];
    const int*   pi    = (const int*)d_in[2];
    const int*   pj    = (const int*)d_in[3];
    const int*   nb    = (const int*)d_in[4];
    const int*   ni    = (const int*)d_in[5];
    const int*   nj    = (const int*)d_in[6];
    const int    P     = in_sizes[1];

    normalize_kernel<<<dim3(Nc / TN, Bc), 256>>>(feats, pb, pi, pj, nb, ni, nj, P);

    const int nblocks = (2 * P + 63) / 64;      // 64 items (octets) per block
    gather_kernel<<<nblocks, 512>>>(P, (float*)d_out);
}

// round 11
// speedup vs baseline: 1.1086x; 1.1086x over previous
#include <cuda_runtime.h>
#include <cuda_fp16.h>
#include <cuda_fp8.h>
#include <math.h>

// Problem shape (fixed by the dataset)
#define Bc 8
#define Dc 128
#define Nc 4096           // 64*64
#define TEMP_INV 10.0f    // 1 / 0.1
#define TN 32             // n-tile width in normalize

// Scratch (allocation-free rule: __device__ globals).
// Normalized features stored fp8 e4m3, permuted-d packing (word L of vector v
// holds d = L, L+32, L+64, L+96). Same permutation on both dot operands ->
// dot unchanged.
__device__ unsigned g_fp8[Bc * Nc * 32];           // 4.2 MB
__device__ uint2 g_pairoff[262144];                // per-item (vec_i, vec_j) uint4-offsets
__device__ float g_partial[16384];                 // per-block partial loss sums

// ---------------------------------------------------------------------------
// Kernel 1: L2-normalize + transpose (B,D,N)->(B,N,D) fp8, PLUS index
// precompute tail (256 pair-items per block -> offsets for the gather).
// ---------------------------------------------------------------------------
__global__ void __launch_bounds__(256, 8) normalize_kernel(
        const float* __restrict__ in,
        const int* __restrict__ pb, const int* __restrict__ pi,
        const int* __restrict__ pj, const int* __restrict__ nb,
        const int* __restrict__ ni, const int* __restrict__ nj, int P) {
    __shared__ float tile[Dc][33];
    __shared__ float psum[32][33];

    const int b      = blockIdx.y;
    const int n_base = blockIdx.x * TN;
    const int t      = threadIdx.x;
    const int r      = t >> 3;
    const int q      = t & 7;

    const float4* src = (const float4*)(in + (size_t)b * Dc * Nc + n_base);

    float4 v[4];
    #pragma unroll
    for (int k = 0; k < 4; k++)
        v[k] = src[(size_t)(r + 32 * k) * (Nc / 4) + q];

    // Index precompute tail (independent of the tile; overlaps load latency)
    {
        const int blk = blockIdx.y * gridDim.x + blockIdx.x;   // 0..1023
        const int item = blk * 256 + t;                        // 0..262143
        if (item < 2 * P) {
            const bool neg = (item >= P);
            const int p  = neg ? item - P : item;
            const int bb = neg ? nb[p] : pb[p];
            const int ii = neg ? ni[p] : pi[p];
            const int jj = neg ? nj[p] : pj[p];
            g_pairoff[item] = make_uint2((unsigned)((bb * Nc + ii) * 8),
                                         (unsigned)((bb * Nc + jj) * 8));
        }
    }

    // Register partial sums of squares for the 4 owned columns
    float s0 = 0.f, s1 = 0.f, s2 = 0.f, s3 = 0.f;
    #pragma unroll
    for (int k = 0; k < 4; k++) {
        s0 += v[k].x * v[k].x;
        s1 += v[k].y * v[k].y;
        s2 += v[k].z * v[k].z;
        s3 += v[k].w * v[k].w;
    }
    psum[r][4 * q + 0] = s0;
    psum[r][4 * q + 1] = s1;
    psum[r][4 * q + 2] = s2;
    psum[r][4 * q + 3] = s3;

    #pragma unroll
    for (int k = 0; k < 4; k++) {
        tile[r + 32 * k][4 * q + 0] = v[k].x;
        tile[r + 32 * k][4 * q + 1] = v[k].y;
        tile[r + 32 * k][4 * q + 2] = v[k].z;
        tile[r + 32 * k][4 * q + 3] = v[k].w;
    }
    __syncthreads();

    // Write phase: warp w writes vectors n0 = w + 8i. All 4 butterfly
    // reductions interleaved -> one overlapped SHFL chain instead of 4 serial.
    const int wid = t >> 5, lane = t & 31;
    float sv[4];
    #pragma unroll
    for (int i = 0; i < 4; i++)
        sv[i] = psum[lane][wid + 8 * i];
    #pragma unroll
    for (int off = 16; off; off >>= 1) {
        #pragma unroll
        for (int i = 0; i < 4; i++)
            sv[i] += __shfl_xor_sync(0xffffffffu, sv[i], off);
    }

    #pragma unroll
    for (int i = 0; i < 4; i++) {
        const int n0 = wid + 8 * i;
        const float inv = 1.0f / fmaxf(sqrtf(sv[i]), 1e-12f);  // F.normalize eps

        // lane owns d = lane + 32k (conflict-free: bank = lane + n0)
        float d0 = tile[lane][n0]      * inv;
        float d1 = tile[lane + 32][n0] * inv;
        float d2 = tile[lane + 64][n0] * inv;
        float d3 = tile[lane + 96][n0] * inv;

        __nv_fp8x2_storage_t lo =
            __nv_cvt_float2_to_fp8x2(make_float2(d0, d1), __NV_SATFINITE, __NV_E4M3);
        __nv_fp8x2_storage_t hi =
            __nv_cvt_float2_to_fp8x2(make_float2(d2, d3), __NV_SATFINITE, __NV_E4M3);
        unsigned w32 = (unsigned)lo | ((unsigned)hi << 16);

        g_fp8[((size_t)(b * Nc + n_base + n0)) * 32 + lane] = w32;
    }
}

// ---------------------------------------------------------------------------
// fp8 u32 -> dot contribution (two half2 fma chains)
// ---------------------------------------------------------------------------
__device__ __forceinline__ __half2 fp8dot_word(unsigned wa, unsigned wc, __half2 acc) {
    __half2 alo = __half2(__nv_cvt_fp8x2_to_halfraw2(
        (__nv_fp8x2_storage_t)(wa & 0xffffu), __NV_E4M3));
    __half2 clo = __half2(__nv_cvt_fp8x2_to_halfraw2(
        (__nv_fp8x2_storage_t)(wc & 0xffffu), __NV_E4M3));
    acc = __hfma2(alo, clo, acc);
    __half2 ahi = __half2(__nv_cvt_fp8x2_to_halfraw2(
        (__nv_fp8x2_storage_t)(wa >> 16), __NV_E4M3));
    __half2 chi = __half2(__nv_cvt_fp8x2_to_halfraw2(
        (__nv_fp8x2_storage_t)(wc >> 16), __NV_E4M3));
    return __hfma2(ahi, chi, acc);
}

// ---------------------------------------------------------------------------
// Kernel 2: octet-per-dot fp8 gather, 2 items per octet (doubled per-thread
// MLP: 2 independent LDG.64 + 4 independent LDG.128; two interleaved shfl
// chains). 512-thread block = 64 octets = 128 items.
// ---------------------------------------------------------------------------
__global__ void gather_kernel(int P, float* __restrict__ out) {
    const int t     = threadIdx.x;
    const int ol    = t & 7;                          // lane within octet
    const int item0 = blockIdx.x * 128 + (t >> 3) * 2;
    const int item1 = item0 + 1;

    float val = 0.f;
    if (item1 < 2 * P) {
        const uint2 off0 = g_pairoff[item0];          // broadcast within octet
        const uint2 off1 = g_pairoff[item1];

        const uint4* g4 = (const uint4*)g_fp8;
        uint4 a0 = g4[off0.x + ol];
        uint4 c0 = g4[off0.y + ol];
        uint4 a1 = g4[off1.x + ol];
        uint4 c1 = g4[off1.y + ol];

        __half2 acc0 = __float2half2_rn(0.f);
        __half2 acc1 = __float2half2_rn(0.f);
        const unsigned* pa0 = &a0.x; const unsigned* pc0 = &c0.x;
        const unsigned* pa1 = &a1.x; const unsigned* pc1 = &c1.x;
        #pragma unroll
        for (int m = 0; m < 4; m++) {
            acc0 = fp8dot_word(pa0[m], pc0[m], acc0);
            acc1 = fp8dot_word(pa1[m], pc1[m], acc1);
        }
        float2 f0 = __half22float2(acc0);
        float2 f1 = __half22float2(acc1);
        float d0 = f0.x + f0.y;
        float d1 = f1.x + f1.y;

        #pragma unroll
        for (int o = 1; o <= 4; o <<= 1) {
            d0 += __shfl_xor_sync(0xffffffffu, d0, o);
            d1 += __shfl_xor_sync(0xffffffffu, d1, o);
        }

        if (ol == 0) {
            float x0 = (item0 >= P) ? d0 * TEMP_INV : -d0 * TEMP_INV;
            float x1 = (item1 >= P) ? d1 * TEMP_INV : -d1 * TEMP_INV;
            val  = fmaxf(x0, 0.f) + log1pf(expf(-fabsf(x0)));
            val += fmaxf(x1, 0.f) + log1pf(expf(-fabsf(x1)));
        }
    } else if (item0 < 2 * P) {      // tail (never taken for P=65536, kept safe)
        const uint2 off0 = g_pairoff[item0];
        const uint4* g4 = (const uint4*)g_fp8;
        uint4 a0 = g4[off0.x + ol];
        uint4 c0 = g4[off0.y + ol];
        __half2 acc0 = __float2half2_rn(0.f);
        const unsigned* pa0 = &a0.x; const unsigned* pc0 = &c0.x;
        #pragma unroll
        for (int m = 0; m < 4; m++) acc0 = fp8dot_word(pa0[m], pc0[m], acc0);
        float2 f0 = __half22float2(acc0);
        float d0 = f0.x + f0.y;
        #pragma unroll
        for (int o = 1; o <= 4; o <<= 1)
            d0 += __shfl_xor_sync(0xffffffffu, d0, o);
        if (ol == 0) {
            float x0 = (item0 >= P) ? d0 * TEMP_INV : -d0 * TEMP_INV;
            val = fmaxf(x0, 0.f) + log1pf(expf(-fabsf(x0)));
        }
    }

    // Block reduction: 64 octet-leader values -> fixed-order tree
    __shared__ float sred[64];
    if (ol == 0) sred[t >> 3] = val;
    __syncthreads();
    if (t < 32) {
        float s = sred[t] + sred[t + 32];
        #pragma unroll
        for (int o = 16; o; o >>= 1)
            s += __shfl_xor_sync(0xffffffffu, s, o);
        if (t == 0) g_partial[blockIdx.x] = s;
    }
}

// ---------------------------------------------------------------------------
// Kernel 3: deterministic final reduction (fixed strided order + tree).
// ---------------------------------------------------------------------------
__global__ void finalize_kernel(int nblocks, int P, float* __restrict__ out) {
    __shared__ float sred[1024];
    float s = 0.f;
    for (int k = threadIdx.x; k < nblocks; k += 1024) s += g_partial[k];
    sred[threadIdx.x] = s;
    __syncthreads();
    #pragma unroll
    for (int stride = 512; stride; stride >>= 1) {
        if (threadIdx.x < stride) sred[threadIdx.x] += sred[threadIdx.x + stride];
        __syncthreads();
    }
    if (threadIdx.x == 0) out[0] = sred[0] / (float)P;
}

extern "C" void kernel_launch(void* const* d_in, const int* in_sizes, int n_in,
                              void* d_out, int out_size) {
    const float* feats = (const float*)d_in[0];
    const int*   pb    = (const int*)d_in[1];
    const int*   pi    = (const int*)d_in[2];
    const int*   pj    = (const int*)d_in[3];
    const int*   nb    = (const int*)d_in[4];
    const int*   ni    = (const int*)d_in[5];
    const int*   nj    = (const int*)d_in[6];
    const int    P     = in_sizes[1];

    normalize_kernel<<<dim3(Nc / TN, Bc), 256>>>(feats, pb, pi, pj, nb, ni, nj, P);

    const int nblocks = (2 * P + 127) / 128;    // 128 items per block
    gather_kernel<<<nblocks, 512>>>(P, (float*)d_out);

    finalize_kernel<<<1, 1024>>>(nblocks, P, (float*)d_out);
}